// round 16
// baseline (speedup 1.0000x reference)
#include <cuda_runtime.h>
#include <cuda_bf16.h>

#define NLEV  256
#define NBINS 2048
#define BPT   6               // ceil(NBINS / 384) bins per thread in LUT build
#define VPT   2               // float4 per stream per thread => 8 elements/thread
#define FBIG  3.402823466e38f

// dynamic smem layout (floats): Tr[(NLEV+1)*32] | ur[NLEV*32] | slut[NBINS shorts] | Ts[NLEV+1]
#define TR_WORDS ((NLEV + 1) * 32)
#define UR_WORDS (NLEV * 32)
#define SMEM_BYTES ((TR_WORDS + UR_WORDS) * 4 + NBINS * 2 + (NLEV + 1) * 4)

// Monotone order-preserving float<->uint key (total order on finite floats).
__device__ __forceinline__ unsigned okey(float f) {
    unsigned u = __float_as_uint(f);
    return (u & 0x80000000u) ? ~u : (u | 0x80000000u);
}
__device__ __forceinline__ float oinv(unsigned k) {
    return __uint_as_float((k & 0x80000000u) ? (k ^ 0x80000000u) : ~k);
}

__global__ void __launch_bounds__(384, 3)
agc_quant_kernel(const float4* __restrict__ in4,
                 const float4* __restrict__ mn4,
                 const float*  __restrict__ uvals,
                 float* __restrict__ out_dq,
                 float* __restrict__ out_sym,
                 int n4, int n)
{
    extern __shared__ float smem[];
    float* Tr   = smem;                                   // replicated thresholds
    float* ur   = Tr + TR_WORDS;                          // replicated values
    short* slut = reinterpret_cast<short*>(ur + UR_WORDS);
    float* Ts   = reinterpret_cast<float*>(slut + NBINS); // scalar thresholds

    const int tid  = threadIdx.x;
    const int lane = tid & 31;
    const int bdim = blockDim.x;                          // 384

    // ---- Exact thresholds: Ts[i-1] = largest v whose tie-break picks symbol
    // i-1 (monotone predicate -> bit-space binary search; rel_err 0 three times).
    if (tid >= 1 && tid < NLEV) {
        float l = __ldg(&uvals[tid - 1]), r = __ldg(&uvals[tid]);
        unsigned klo = okey(l);
        unsigned khi = okey(r);
        #pragma unroll 1
        while (khi - klo > 1u) {
            unsigned km = klo + ((khi - klo) >> 1);
            float vm = oinv(km);
            if (fabsf(vm - l) <= fabsf(vm - r)) klo = km; else khi = km;
        }
        Ts[tid - 1] = oinv(klo);
    }
    if (tid == 0) { Ts[NLEV - 1] = FBIG; Ts[NLEV] = FBIG; }
    __syncthreads();

    // ---- Replicated tables (broadcast fills, conflict-free use)
    for (int i = tid; i < TR_WORDS; i += bdim) Tr[i] = Ts[i >> 5];
    for (int i = tid; i < UR_WORDS; i += bdim) ur[i] = uvals[i >> 5];
    __syncthreads();

    const float* Trl = Tr + lane;
    const float* url = ur + lane;

    const float lo    = __ldg(&uvals[0]);
    const float hi    = __ldg(&uvals[NLEV - 1]);
    const float w     = (hi - lo) * (1.0f / NBINS);
    const float inv_w = (float)NBINS / (hi - lo);
    const float c0    = -lo * inv_w;                      // bin = trunc(fmaf(v,inv_w,c0))

    // ---- slut[b] = count(T < fmaf(b-1, w, lo)) : one-bin-conservative lower
    // bound of count(T < v) for any v whose computed bin is b. Incremental.
    {
        const int b0 = tid * BPT;
        if (b0 < NBINS) {
            float bs = fmaf((float)(b0 - 1), w, lo);
            int pos = 0;
            #pragma unroll
            for (int s = 128; s >= 1; s >>= 1) {
                if (Trl[(pos + s - 1) << 5] < bs) pos += s;
            }
            if (pos > NLEV - 1) pos = NLEV - 1;
            slut[b0] = (short)pos;
            #pragma unroll
            for (int j = 1; j < BPT; j++) {
                int b = b0 + j;
                if (b >= NBINS) break;
                bs = fmaf((float)(b - 1), w, lo);
                while (Trl[pos << 5] < bs) ++pos;         // FBIG rows bound the walk
                slut[b] = (short)pos;
            }
        }
    }
    __syncthreads();

    const int tile  = bdim * VPT;
    const int gstep = gridDim.x * tile;

    int base = blockIdx.x * tile + tid;

    // ---- software pipeline: prefetch next iteration's loads before compute ----
    float4 xa[VPT], ma[VPT];
    bool fastA = (base < n4) && (base + (VPT - 1) * bdim < n4);
    if (fastA) {
        #pragma unroll
        for (int j = 0; j < VPT; j++) xa[j] = __ldcs(&in4[base + j * bdim]);
        #pragma unroll
        for (int j = 0; j < VPT; j++) ma[j] = __ldcs(&mn4[base + j * bdim]);
    }

    while (base < n4) {
        const int nbase = base + gstep;

        float4 xb[VPT], mb[VPT];
        const bool fastB = (nbase < n4) && (nbase + (VPT - 1) * bdim < n4);
        if (fastB) {
            #pragma unroll
            for (int j = 0; j < VPT; j++) xb[j] = __ldcs(&in4[nbase + j * bdim]);
            #pragma unroll
            for (int j = 0; j < VPT; j++) mb[j] = __ldcs(&mn4[nbase + j * bdim]);
        }

        if (fastA) {
            float v[4 * VPT];
            #pragma unroll
            for (int j = 0; j < VPT; j++) {
                v[4*j+0] = xa[j].x - ma[j].x;
                v[4*j+1] = xa[j].y - ma[j].y;
                v[4*j+2] = xa[j].z - ma[j].z;
                v[4*j+3] = xa[j].w - ma[j].w;
            }

            int p[4 * VPT];
            #pragma unroll
            for (int e = 0; e < 4 * VPT; e++) {
                int b = (int)fmaf(v[e], inv_w, c0);
                b = b < 0 ? 0 : (b > NBINS - 1 ? NBINS - 1 : b);
                p[e] = slut[b];                           // conservative seed
            }

            float dq[4 * VPT], sy[4 * VPT];
            #pragma unroll
            for (int e = 0; e < 4 * VPT; e++) {
                int q = p[e];
                while (Trl[q << 5] < v[e]) ++q;           // exact count(T < v) = symbol
                sy[e] = (float)q;                         // no clamp: T[255]=FBIG
                dq[e] = url[q << 5];                      // u[symbol]
            }
            #pragma unroll
            for (int j = 0; j < VPT; j++) {
                __stcs(&reinterpret_cast<float4*>(out_dq)[base + j * bdim],
                       make_float4(dq[4*j+0] + ma[j].x, dq[4*j+1] + ma[j].y,
                                   dq[4*j+2] + ma[j].z, dq[4*j+3] + ma[j].w));
                __stcs(&reinterpret_cast<float4*>(out_sym)[base + j * bdim],
                       make_float4(sy[4*j+0], sy[4*j+1], sy[4*j+2], sy[4*j+3]));
            }
        } else {
            // guarded path (last partial tile)
            #pragma unroll
            for (int j = 0; j < VPT; j++) {
                int i = base + j * bdim;
                if (i >= n4) break;
                float4 x = in4[i];
                float4 m = mn4[i];
                float vv[4] = { x.x - m.x, x.y - m.y, x.z - m.z, x.w - m.w };
                float dq[4], sy[4];
                #pragma unroll
                for (int k = 0; k < 4; k++) {
                    int b = (int)fmaf(vv[k], inv_w, c0);
                    b = b < 0 ? 0 : (b > NBINS - 1 ? NBINS - 1 : b);
                    int q = slut[b];
                    while (Trl[q << 5] < vv[k]) ++q;
                    sy[k] = (float)q;
                    dq[k] = url[q << 5];
                }
                reinterpret_cast<float4*>(out_dq)[i] =
                    make_float4(dq[0] + m.x, dq[1] + m.y, dq[2] + m.z, dq[3] + m.w);
                reinterpret_cast<float4*>(out_sym)[i] =
                    make_float4(sy[0], sy[1], sy[2], sy[3]);
            }
        }

        base  = nbase;
        fastA = fastB;
        #pragma unroll
        for (int j = 0; j < VPT; j++) { xa[j] = xb[j]; ma[j] = mb[j]; }
    }

    // Scalar float tail (n % 4 != 0) — block 0 only.
    if (blockIdx.x == 0) {
        const float* in1 = reinterpret_cast<const float*>(in4);
        const float* mn1 = reinterpret_cast<const float*>(mn4);
        for (int i = n4 * 4 + tid; i < n; i += bdim) {
            float vv = in1[i] - mn1[i];
            int b = (int)fmaf(vv, inv_w, c0);
            b = b < 0 ? 0 : (b > NBINS - 1 ? NBINS - 1 : b);
            int q = slut[b];
            while (Trl[q << 5] < vv) ++q;
            out_sym[i] = (float)q;
            out_dq[i]  = url[q << 5] + mn1[i];
        }
    }
}

extern "C" void kernel_launch(void* const* d_in, const int* in_sizes, int n_in,
                              void* d_out, int out_size)
{
    const float* inputs = (const float*)d_in[0];
    const float* means  = (const float*)d_in[1];
    const float* uvals  = (const float*)d_in[2];
    float* out = (float*)d_out;

    const int n  = out_size / 2;
    const int n4 = n / 4;

    float* out_dq  = out;
    float* out_sym = out + n;

    cudaFuncSetAttribute(agc_quant_kernel,
                         cudaFuncAttributeMaxDynamicSharedMemorySize, SMEM_BYTES);

    const int threads = 384;
    int blocks = 444;                        // 3 CTAs/SM on 148 SMs, pipelined grid-stride
    int maxb = (n4 + threads * VPT - 1) / (threads * VPT);
    if (blocks > maxb && maxb > 0) blocks = maxb;
    if (blocks < 1) blocks = 1;

    agc_quant_kernel<<<blocks, threads, SMEM_BYTES>>>(
        (const float4*)inputs, (const float4*)means, uvals,
        out_dq, out_sym, n4, n);
}

// round 17
// speedup vs baseline: 1.1374x; 1.1374x over previous
#include <cuda_runtime.h>
#include <cuda_bf16.h>

#define NLEV  256
#define NBINS 4096
#define BPT   (NBINS / 512)   // 8 consecutive bins per thread in LUT build
#define VPT   2               // float4 per stream per thread => 8 elements/thread
#define FBIG  3.402823466e38f

__global__ void __launch_bounds__(512, 2)
agc_quant_kernel(const float4* __restrict__ in4,
                 const float4* __restrict__ mn4,
                 const float*  __restrict__ uvals,
                 float* __restrict__ out_dq,
                 float* __restrict__ out_sym,
                 int n4, int n)
{
    __shared__ float us[(NLEV + 1) * 32];        // replicated codebook + FBIG pad row
    __shared__ __align__(16) short slut[NBINS];  // 8 KB conservative seed LUT

    const int tid  = threadIdx.x;
    const int lane = tid & 31;
    const int bdim = blockDim.x;                 // 512

    for (int i = tid; i < NLEV * 32; i += bdim)
        us[i] = uvals[i >> 5];
    for (int i = tid; i < 32; i += bdim)
        us[NLEV * 32 + i] = FBIG;                // pad: every scan terminates
    __syncthreads();

    const float* usl = us + lane;                // lane-hoisted base (conflict-free)

    const float lo    = usl[0];
    const float hi    = usl[(NLEV - 1) << 5];
    const float w     = (hi - lo) * (1.0f / NBINS);
    const float inv_w = (float)NBINS / (hi - lo);
    const float c0    = -lo * inv_w;             // bin = trunc(fmaf(v, inv_w, c0))

    // slut[b] = count(u < fmaf(b-1, w, lo)) : one-bin-conservative lower bound.
    // Incremental build: one binary search per 8 consecutive bins + forward walk.
    {
        const int b0 = tid * BPT;
        float bs = fmaf((float)(b0 - 1), w, lo);
        int pos = 0;
        #pragma unroll
        for (int s = 128; s >= 1; s >>= 1) {
            if (usl[(pos + s - 1) << 5] < bs) pos += s;
        }
        slut[b0] = (short)pos;
        #pragma unroll
        for (int j = 1; j < BPT; j++) {
            bs = fmaf((float)(b0 + j - 1), w, lo);
            while (usl[pos << 5] < bs) ++pos;    // pad row bounds the walk
            slut[b0 + j] = (short)pos;
        }
    }
    __syncthreads();

    const int tile  = bdim * VPT;
    const int gstep = gridDim.x * tile;

    int base = blockIdx.x * tile + tid;

    // ---- software pipeline: prefetch next iteration's loads before compute ----
    float4 xa[VPT], ma[VPT];
    bool fastA = (base < n4) && (base + (VPT - 1) * bdim < n4);
    if (fastA) {
        #pragma unroll
        for (int j = 0; j < VPT; j++) xa[j] = __ldcs(&in4[base + j * bdim]);
        #pragma unroll
        for (int j = 0; j < VPT; j++) ma[j] = __ldcs(&mn4[base + j * bdim]);
    }

    while (base < n4) {
        const int nbase = base + gstep;

        float4 xb[VPT], mb[VPT];
        const bool fastB = (nbase < n4) && (nbase + (VPT - 1) * bdim < n4);
        if (fastB) {
            #pragma unroll
            for (int j = 0; j < VPT; j++) xb[j] = __ldcs(&in4[nbase + j * bdim]);
            #pragma unroll
            for (int j = 0; j < VPT; j++) mb[j] = __ldcs(&mn4[nbase + j * bdim]);
        }

        if (fastA) {
            float v[4 * VPT];
            #pragma unroll
            for (int j = 0; j < VPT; j++) {
                v[4*j+0] = xa[j].x - ma[j].x;
                v[4*j+1] = xa[j].y - ma[j].y;
                v[4*j+2] = xa[j].z - ma[j].z;
                v[4*j+3] = xa[j].w - ma[j].w;
            }

            int p[4 * VPT];
            #pragma unroll
            for (int e = 0; e < 4 * VPT; e++) {
                int b = (int)fmaf(v[e], inv_w, c0);
                b = b < 0 ? 0 : (b > NBINS - 1 ? NBINS - 1 : b);
                p[e] = slut[b];                         // conservative seed
            }

            float dq[4 * VPT], sy[4 * VPT];
            #pragma unroll
            for (int e = 0; e < 4 * VPT; e++) {
                int q = p[e];
                float r = usl[q << 5];
                while (r < v[e]) { ++q; r = usl[q << 5]; }  // exact count(u < v)
                // r == us[q] is the RIGHT neighbor whenever q == clip(q,1,255).
                int c = q < 1 ? 1 : (q > NLEV - 1 ? NLEV - 1 : q);
                float right = r;
                if (c != q) right = usl[c << 5];            // rare: predicated reload
                float left = usl[(c - 1) << 5];
                bool tl = fabsf(v[e] - left) <= fabsf(v[e] - right);
                sy[e] = (float)(tl ? c - 1 : c);
                dq[e] = tl ? left : right;
            }
            #pragma unroll
            for (int j = 0; j < VPT; j++) {
                __stcs(&reinterpret_cast<float4*>(out_dq)[base + j * bdim],
                       make_float4(dq[4*j+0] + ma[j].x, dq[4*j+1] + ma[j].y,
                                   dq[4*j+2] + ma[j].z, dq[4*j+3] + ma[j].w));
                __stcs(&reinterpret_cast<float4*>(out_sym)[base + j * bdim],
                       make_float4(sy[4*j+0], sy[4*j+1], sy[4*j+2], sy[4*j+3]));
            }
        } else {
            // guarded path (last partial tile)
            #pragma unroll
            for (int j = 0; j < VPT; j++) {
                int i = base + j * bdim;
                if (i >= n4) break;
                float4 x = in4[i];
                float4 m = mn4[i];
                float vv[4] = { x.x - m.x, x.y - m.y, x.z - m.z, x.w - m.w };
                float dq[4], sy[4];
                #pragma unroll
                for (int k = 0; k < 4; k++) {
                    int b = (int)fmaf(vv[k], inv_w, c0);
                    b = b < 0 ? 0 : (b > NBINS - 1 ? NBINS - 1 : b);
                    int q = slut[b];
                    while (usl[q << 5] < vv[k]) ++q;
                    int c = q < 1 ? 1 : (q > NLEV - 1 ? NLEV - 1 : q);
                    float left  = usl[(c - 1) << 5];
                    float right = usl[c << 5];
                    bool tl = fabsf(vv[k] - left) <= fabsf(vv[k] - right);
                    sy[k] = (float)(tl ? c - 1 : c);
                    dq[k] = tl ? left : right;
                }
                reinterpret_cast<float4*>(out_dq)[i] =
                    make_float4(dq[0] + m.x, dq[1] + m.y, dq[2] + m.z, dq[3] + m.w);
                reinterpret_cast<float4*>(out_sym)[i] =
                    make_float4(sy[0], sy[1], sy[2], sy[3]);
            }
        }

        base  = nbase;
        fastA = fastB;
        #pragma unroll
        for (int j = 0; j < VPT; j++) { xa[j] = xb[j]; ma[j] = mb[j]; }
    }

    // Scalar float tail (n % 4 != 0) — block 0 only.
    if (blockIdx.x == 0) {
        const float* in1 = reinterpret_cast<const float*>(in4);
        const float* mn1 = reinterpret_cast<const float*>(mn4);
        for (int i = n4 * 4 + tid; i < n; i += bdim) {
            float vv = in1[i] - mn1[i];
            int b = (int)fmaf(vv, inv_w, c0);
            b = b < 0 ? 0 : (b > NBINS - 1 ? NBINS - 1 : b);
            int q = slut[b];
            while (usl[q << 5] < vv) ++q;
            int c = q < 1 ? 1 : (q > NLEV - 1 ? NLEV - 1 : q);
            float left  = usl[(c - 1) << 5];
            float right = usl[c << 5];
            bool tl = fabsf(vv - left) <= fabsf(vv - right);
            out_sym[i] = (float)(tl ? c - 1 : c);
            out_dq[i]  = (tl ? left : right) + mn1[i];
        }
    }
}

extern "C" void kernel_launch(void* const* d_in, const int* in_sizes, int n_in,
                              void* d_out, int out_size)
{
    const float* inputs = (const float*)d_in[0];
    const float* means  = (const float*)d_in[1];
    const float* uvals  = (const float*)d_in[2];
    float* out = (float*)d_out;

    const int n  = out_size / 2;
    const int n4 = n / 4;

    float* out_dq  = out;
    float* out_sym = out + n;

    const int threads = 512;
    int blocks = 296;                        // 2 CTAs/SM on 148 SMs, pipelined grid-stride
    int maxb = (n4 + threads * VPT - 1) / (threads * VPT);
    if (blocks > maxb && maxb > 0) blocks = maxb;
    if (blocks < 1) blocks = 1;

    agc_quant_kernel<<<blocks, threads>>>(
        (const float4*)inputs, (const float4*)means, uvals,
        out_dq, out_sym, n4, n);
}